// round 4
// baseline (speedup 1.0000x reference)
#include <cuda_runtime.h>
#include <math.h>

#define DIMC 512
#define HC   1024
#define BC   64
#define VC   64
#define JT   8

__device__ __align__(16) float g_pre[3 * BC * HC];

__device__ __forceinline__ float ex2_approx(float x) {
    float y; asm("ex2.approx.f32 %0, %1;" : "=f"(y) : "f"(x)); return y;
}
__device__ __forceinline__ float rcp_approx(float x) {
    float y; asm("rcp.approx.f32 %0, %1;" : "=f"(y) : "f"(x)); return y;
}
__device__ __forceinline__ unsigned long long pk2(float lo, float hi) {
    unsigned long long r; asm("mov.b64 %0, {%1,%2};" : "=l"(r) : "f"(lo), "f"(hi)); return r;
}
__device__ __forceinline__ void upk2(unsigned long long v, float& lo, float& hi) {
    asm("mov.b64 {%0,%1}, %2;" : "=f"(lo), "=f"(hi) : "l"(v));
}
__device__ __forceinline__ unsigned long long add2(unsigned long long a, unsigned long long b) {
    unsigned long long r; asm("add.rn.f32x2 %0, %1, %2;" : "=l"(r) : "l"(a), "l"(b)); return r;
}
__device__ __forceinline__ unsigned long long mul2(unsigned long long a, unsigned long long b) {
    unsigned long long r; asm("mul.rn.f32x2 %0, %1, %2;" : "=l"(r) : "l"(a), "l"(b)); return r;
}
__device__ __forceinline__ unsigned long long fma2(unsigned long long a, unsigned long long b, unsigned long long c) {
    unsigned long long r; asm("fma.rn.f32x2 %0, %1, %2, %3;" : "=l"(r) : "l"(a), "l"(b), "l"(c)); return r;
}

// tanh-form GELU sigmoid-arg constants, pre-multiplied by -log2(e):
// a(t) = t*(-2.3022079 - 0.1029428*t^2);  sigma = 1/(1+2^a);  gelu = t*sigma
#define K1F (-2.3022079f)
#define K3F (-0.1029428f)

// ---------------------------------------------------------------------------
// Kernel 1: pre-activations. grid = 3*32 = 96 blocks (m, 32-col tile).
// thread = 1 row x 8 cols; A-load is 8-bank broadcast (conflict-free),
// W-load is two warp-uniform LDS.128 broadcasts.
// ---------------------------------------------------------------------------
__global__ __launch_bounds__(256) void gemm_pre_kernel(
        const float* __restrict__ state, const float* __restrict__ action,
        const float* __restrict__ embed, const float* __restrict__ W1) {
    const int m  = blockIdx.x >> 5;   // 0..2
    const int ct = blockIdx.x & 31;   // cols ct*32 .. +32
    const int tid = threadIdx.x;

    __shared__ float As[64][33];
    __shared__ __align__(16) float Ws[32][36];

    const int r  = tid >> 2;          // row 0..63
    const int cg = tid & 3;           // col group: cols cg*8 .. +8

    float acc[8];
#pragma unroll
    for (int i = 0; i < 8; ++i) acc[i] = 0.0f;

    const float* Wbase = W1 + (size_t)(m * DIMC) * HC + ct * 32;

    for (int k0 = 0; k0 < DIMC; k0 += 32) {
        for (int t = tid; t < 64 * 32; t += 256) {
            int rr = t >> 5, k = t & 31;
            float a;
            if (m == 2) a = state[rr * DIMC + k0 + k] + action[rr * DIMC + k0 + k];
            else        a = embed[rr * DIMC + k0 + k];
            As[rr][k] = a;
        }
        for (int t = tid; t < 32 * 32; t += 256) {
            int k = t >> 5, c = t & 31;
            Ws[k][c] = Wbase[(size_t)(k0 + k) * HC + c];
        }
        __syncthreads();
#pragma unroll
        for (int k = 0; k < 32; ++k) {
            float a = As[r][k];
            float4 w0 = *reinterpret_cast<const float4*>(&Ws[k][cg * 8]);
            float4 w1 = *reinterpret_cast<const float4*>(&Ws[k][cg * 8 + 4]);
            acc[0] = fmaf(a, w0.x, acc[0]);
            acc[1] = fmaf(a, w0.y, acc[1]);
            acc[2] = fmaf(a, w0.z, acc[2]);
            acc[3] = fmaf(a, w0.w, acc[3]);
            acc[4] = fmaf(a, w1.x, acc[4]);
            acc[5] = fmaf(a, w1.y, acc[5]);
            acc[6] = fmaf(a, w1.z, acc[6]);
            acc[7] = fmaf(a, w1.w, acc[7]);
        }
        __syncthreads();
    }

    float* out = g_pre + (size_t)(m * BC) * HC + (size_t)r * HC + ct * 32 + cg * 8;
    *reinterpret_cast<float4*>(out)     = make_float4(acc[0], acc[1], acc[2], acc[3]);
    *reinterpret_cast<float4*>(out + 4) = make_float4(acc[4], acc[5], acc[6], acc[7]);
}

// ---------------------------------------------------------------------------
// Kernel 2: scores. grid=512 (i, j-tile of 8), 256 thr = 8 warps, warp-per-b.
// Packed f32x2 arg math, 1 rcp per h-pair, scalar accumulators,
// per-warp partials live in smem (reg relief -> 5 blocks/SM).
// ---------------------------------------------------------------------------
__global__ __launch_bounds__(256, 5) void score_kernel(
        const float* __restrict__ b1, const float* __restrict__ W2,
        const float* __restrict__ b2, float* __restrict__ out) {
    const int i  = blockIdx.x >> 3;
    const int jt = blockIdx.x & 7;

    __shared__ __align__(16) float ce_s[JT][HC];
    __shared__ __align__(16) float w2s[HC];
    __shared__ float red[8][JT];

    const int tid  = threadIdx.x;
    const int warp = tid >> 5;
    const int lane = tid & 31;

    const float* cause  = g_pre;
    const float* effect = g_pre + BC * HC;
    const float* ctx    = g_pre + 2 * BC * HC;

    if (tid < 8 * JT) red[tid >> 3][tid & 7] = 0.0f;

    {
        const float4* c4 = reinterpret_cast<const float4*>(cause + i * HC);
        const float4* b4 = reinterpret_cast<const float4*>(b1);
        for (int t = tid; t < JT * HC / 4; t += 256) {
            int j = t >> 8, v = t & 255;
            float4 e4 = reinterpret_cast<const float4*>(effect + (jt * JT + j) * HC)[v];
            float4 cc = c4[v], bb = b4[v];
            float4 rr;
            rr.x = cc.x + e4.x + bb.x;
            rr.y = cc.y + e4.y + bb.y;
            rr.z = cc.z + e4.z + bb.z;
            rr.w = cc.w + e4.w + bb.w;
            reinterpret_cast<float4*>(ce_s[j])[v] = rr;
        }
        for (int t = tid; t < HC / 4; t += 256)
            reinterpret_cast<float4*>(w2s)[t] = reinterpret_cast<const float4*>(W2)[t];
    }
    __syncthreads();

    const unsigned long long K1p = pk2(K1F, K1F);
    const unsigned long long K3p = pk2(K3F, K3F);
    const float bias2 = b2[0];

    for (int bi = 0; bi < 8; ++bi) {
        const int b = bi * 8 + warp;
        const ulonglong2* ctx2 = reinterpret_cast<const ulonglong2*>(ctx + (size_t)b * HC);
        const float4*     w24  = reinterpret_cast<const float4*>(w2s);

        float acc[JT];
#pragma unroll
        for (int j = 0; j < JT; ++j) acc[j] = 0.0f;

        for (int v = lane; v < HC / 4; v += 32) {
            const ulonglong2 x2 = ctx2[v];
            const float4     w4 = w24[v];
#pragma unroll
            for (int j = 0; j < JT; ++j) {
                const ulonglong2 c2 = reinterpret_cast<const ulonglong2*>(ce_s[j])[v];
                // lo pair (h, h+1)
                {
                    unsigned long long t2 = add2(x2.x, c2.x);
                    unsigned long long s2 = mul2(t2, t2);
                    unsigned long long p2 = fma2(s2, K3p, K1p);
                    unsigned long long a2 = mul2(p2, t2);
                    float al, ah; upk2(a2, al, ah);
                    al = fminf(al, 80.0f);
                    ah = fminf(ah, 80.0f);
                    float dl = ex2_approx(al) + 1.0f;
                    float dh = ex2_approx(ah) + 1.0f;
                    float R  = rcp_approx(dl * dh);
                    float tl, th; upk2(t2, tl, th);
                    float gl = (tl * dh) * R;
                    float gh = (th * dl) * R;
                    acc[j] = fmaf(w4.x, gl, acc[j]);
                    acc[j] = fmaf(w4.y, gh, acc[j]);
                }
                // hi pair (h+2, h+3)
                {
                    unsigned long long t2 = add2(x2.y, c2.y);
                    unsigned long long s2 = mul2(t2, t2);
                    unsigned long long p2 = fma2(s2, K3p, K1p);
                    unsigned long long a2 = mul2(p2, t2);
                    float al, ah; upk2(a2, al, ah);
                    al = fminf(al, 80.0f);
                    ah = fminf(ah, 80.0f);
                    float dl = ex2_approx(al) + 1.0f;
                    float dh = ex2_approx(ah) + 1.0f;
                    float R  = rcp_approx(dl * dh);
                    float tl, th; upk2(t2, tl, th);
                    float gl = (tl * dh) * R;
                    float gh = (th * dl) * R;
                    acc[j] = fmaf(w4.z, gl, acc[j]);
                    acc[j] = fmaf(w4.w, gh, acc[j]);
                }
            }
        }

#pragma unroll
        for (int off = 16; off; off >>= 1)
#pragma unroll
            for (int j = 0; j < JT; ++j)
                acc[j] += __shfl_xor_sync(0xffffffffu, acc[j], off);

        if (lane == 0) {
#pragma unroll
            for (int j = 0; j < JT; ++j) {
                float logit = acc[j] + bias2;
                float en = ex2_approx(-1.44269504f * logit);
                red[warp][j] += rcp_approx(1.0f + en);
            }
        }
    }

    __syncthreads();
    if (tid < JT) {
        float s = 0.0f;
#pragma unroll
        for (int w = 0; w < 8; ++w) s += red[w][tid];
        out[i * VC + jt * JT + tid] = s * (1.0f / BC);
    }
}

// ---------------------------------------------------------------------------
extern "C" void kernel_launch(void* const* d_in, const int* in_sizes, int n_in,
                              void* d_out, int out_size) {
    const float* state  = (const float*)d_in[0];
    const float* action = (const float*)d_in[1];
    const float* embed  = (const float*)d_in[2];
    const float* W1     = (const float*)d_in[3];
    const float* b1     = (const float*)d_in[4];
    const float* W2     = (const float*)d_in[5];
    const float* b2     = (const float*)d_in[6];
    float* out          = (float*)d_out;

    gemm_pre_kernel<<<96, 256>>>(state, action, embed, W1);
    score_kernel<<<VC * (VC / JT), 256>>>(b1, W2, b2, out);
}

// round 5
// speedup vs baseline: 1.8976x; 1.8976x over previous
#include <cuda_runtime.h>
#include <math.h>

#define DIMC 512
#define HC   1024
#define BC   64
#define VC   64
#define JT   8

__device__ __align__(16) float g_pre[3 * BC * HC];

__device__ __forceinline__ float ex2_approx(float x) {
    float y; asm("ex2.approx.f32 %0, %1;" : "=f"(y) : "f"(x)); return y;
}
__device__ __forceinline__ float rcp_approx(float x) {
    float y; asm("rcp.approx.f32 %0, %1;" : "=f"(y) : "f"(x)); return y;
}
__device__ __forceinline__ float tanh_approx(float x) {
    float y; asm("tanh.approx.f32 %0, %1;" : "=f"(y) : "f"(x)); return y;
}
__device__ __forceinline__ unsigned long long pk2(float lo, float hi) {
    unsigned long long r; asm("mov.b64 %0, {%1,%2};" : "=l"(r) : "f"(lo), "f"(hi)); return r;
}
__device__ __forceinline__ void upk2(unsigned long long v, float& lo, float& hi) {
    asm("mov.b64 {%0,%1}, %2;" : "=f"(lo), "=f"(hi) : "l"(v));
}
__device__ __forceinline__ unsigned long long add2(unsigned long long a, unsigned long long b) {
    unsigned long long r; asm("add.rn.f32x2 %0, %1, %2;" : "=l"(r) : "l"(a), "l"(b)); return r;
}
__device__ __forceinline__ unsigned long long mul2(unsigned long long a, unsigned long long b) {
    unsigned long long r; asm("mul.rn.f32x2 %0, %1, %2;" : "=l"(r) : "l"(a), "l"(b)); return r;
}
__device__ __forceinline__ unsigned long long fma2(unsigned long long a, unsigned long long b, unsigned long long c) {
    unsigned long long r; asm("fma.rn.f32x2 %0, %1, %2, %3;" : "=l"(r) : "l"(a), "l"(b), "l"(c)); return r;
}

// Hendrycks tanh-form GELU: gelu(t) = 0.5*t*(1 + tanh(t*(C1 + C3*t^2)))
#define C1F (0.7978845608f)
#define C3F (0.0356774081f)   // 0.7978845608 * 0.044715

// ---------------------------------------------------------------------------
// Kernel 1: pre-activations, register-prefetch double buffered.
// grid = 3*32 = 96 blocks (m, 32-col tile), 256 threads.
// ---------------------------------------------------------------------------
__global__ __launch_bounds__(256) void gemm_pre_kernel(
        const float* __restrict__ state, const float* __restrict__ action,
        const float* __restrict__ embed, const float* __restrict__ W1) {
    const int m  = blockIdx.x >> 5;   // 0..2
    const int ct = blockIdx.x & 31;   // cols ct*32 .. +32
    const int tid = threadIdx.x;

    __shared__ float As[64][33];
    __shared__ __align__(16) float Ws[32][36];

    const int r  = tid >> 2;          // row 0..63
    const int cg = tid & 3;           // cols cg*8 .. +8

    float acc[8];
#pragma unroll
    for (int i = 0; i < 8; ++i) acc[i] = 0.0f;

    const float* Wbase = W1 + (size_t)(m * DIMC) * HC + ct * 32;

    float a_pref[8];
    float w_pref[4];

    // prefetch chunk 0
#pragma unroll
    for (int i = 0; i < 8; ++i) {
        int idx = tid + i * 256;          // 0..2047
        int rr = idx >> 5, k = idx & 31;
        if (m == 2) a_pref[i] = state[rr * DIMC + k] + action[rr * DIMC + k];
        else        a_pref[i] = embed[rr * DIMC + k];
    }
#pragma unroll
    for (int i = 0; i < 4; ++i) {
        int idx = tid + i * 256;          // 0..1023
        int k = idx >> 5, c = idx & 31;
        w_pref[i] = Wbase[(size_t)k * HC + c];
    }

    for (int ch = 0; ch < DIMC / 32; ++ch) {
        __syncthreads();
#pragma unroll
        for (int i = 0; i < 8; ++i) {
            int idx = tid + i * 256;
            As[idx >> 5][idx & 31] = a_pref[i];
        }
#pragma unroll
        for (int i = 0; i < 4; ++i) {
            int idx = tid + i * 256;
            Ws[idx >> 5][idx & 31] = w_pref[i];
        }
        __syncthreads();

        if (ch < DIMC / 32 - 1) {
            const int k0 = (ch + 1) * 32;
#pragma unroll
            for (int i = 0; i < 8; ++i) {
                int idx = tid + i * 256;
                int rr = idx >> 5, k = idx & 31;
                if (m == 2) a_pref[i] = state[rr * DIMC + k0 + k] + action[rr * DIMC + k0 + k];
                else        a_pref[i] = embed[rr * DIMC + k0 + k];
            }
#pragma unroll
            for (int i = 0; i < 4; ++i) {
                int idx = tid + i * 256;
                int k = idx >> 5, c = idx & 31;
                w_pref[i] = Wbase[(size_t)(k0 + k) * HC + c];
            }
        }

#pragma unroll
        for (int k = 0; k < 32; ++k) {
            float a = As[r][k];
            float4 w0 = *reinterpret_cast<const float4*>(&Ws[k][cg * 8]);
            float4 w1 = *reinterpret_cast<const float4*>(&Ws[k][cg * 8 + 4]);
            acc[0] = fmaf(a, w0.x, acc[0]);
            acc[1] = fmaf(a, w0.y, acc[1]);
            acc[2] = fmaf(a, w0.z, acc[2]);
            acc[3] = fmaf(a, w0.w, acc[3]);
            acc[4] = fmaf(a, w1.x, acc[4]);
            acc[5] = fmaf(a, w1.y, acc[5]);
            acc[6] = fmaf(a, w1.z, acc[6]);
            acc[7] = fmaf(a, w1.w, acc[7]);
        }
    }

    float* out = g_pre + (size_t)(m * BC) * HC + (size_t)r * HC + ct * 32 + cg * 8;
    *reinterpret_cast<float4*>(out)     = make_float4(acc[0], acc[1], acc[2], acc[3]);
    *reinterpret_cast<float4*>(out + 4) = make_float4(acc[4], acc[5], acc[6], acc[7]);
}

// ---------------------------------------------------------------------------
// Kernel 2: scores. grid=512 (i, j-tile of 8), 256 thr = 8 warps, warp-per-b.
// Packed f32x2 arg math + MUFU.TANH: 3.5 fma + 1 MUFU per eval.
// ---------------------------------------------------------------------------
__global__ __launch_bounds__(256) void score_kernel(
        const float* __restrict__ b1, const float* __restrict__ W2,
        const float* __restrict__ b2, float* __restrict__ out) {
    const int i  = blockIdx.x >> 3;
    const int jt = blockIdx.x & 7;

    __shared__ __align__(16) float ce_s[JT][HC];
    __shared__ __align__(16) float w2s[HC];
    __shared__ float red[8][JT];

    const int tid  = threadIdx.x;
    const int warp = tid >> 5;
    const int lane = tid & 31;

    const float* cause  = g_pre;
    const float* effect = g_pre + BC * HC;
    const float* ctx    = g_pre + 2 * BC * HC;

    if (tid < 8 * JT) red[tid >> 3][tid & 7] = 0.0f;

    {
        const float4* c4 = reinterpret_cast<const float4*>(cause + i * HC);
        const float4* b4 = reinterpret_cast<const float4*>(b1);
        for (int t = tid; t < JT * HC / 4; t += 256) {
            int j = t >> 8, v = t & 255;
            float4 e4 = reinterpret_cast<const float4*>(effect + (jt * JT + j) * HC)[v];
            float4 cc = c4[v], bb = b4[v];
            float4 rr;
            rr.x = cc.x + e4.x + bb.x;
            rr.y = cc.y + e4.y + bb.y;
            rr.z = cc.z + e4.z + bb.z;
            rr.w = cc.w + e4.w + bb.w;
            reinterpret_cast<float4*>(ce_s[j])[v] = rr;
        }
        for (int t = tid; t < HC / 4; t += 256)
            reinterpret_cast<float4*>(w2s)[t] = reinterpret_cast<const float4*>(W2)[t];
    }
    __syncthreads();

    const unsigned long long C1p = pk2(C1F, C1F);
    const unsigned long long C3p = pk2(C3F, C3F);
    const unsigned long long H2p = pk2(0.5f, 0.5f);
    const float bias2 = b2[0];

    for (int bi = 0; bi < 8; ++bi) {
        const int b = bi * 8 + warp;
        const ulonglong2* ctx2 = reinterpret_cast<const ulonglong2*>(ctx + (size_t)b * HC);
        const ulonglong2* w22  = reinterpret_cast<const ulonglong2*>(w2s);

        unsigned long long acc2[JT];
#pragma unroll
        for (int j = 0; j < JT; ++j) acc2[j] = 0ull;

        for (int v = lane; v < HC / 4; v += 32) {
            const ulonglong2 x2 = ctx2[v];
            const ulonglong2 w2 = w22[v];
#pragma unroll
            for (int j = 0; j < JT; ++j) {
                const ulonglong2 c2 = reinterpret_cast<const ulonglong2*>(ce_s[j])[v];
#pragma unroll
                for (int p = 0; p < 2; ++p) {
                    unsigned long long xp = p ? x2.y : x2.x;
                    unsigned long long cp = p ? c2.y : c2.x;
                    unsigned long long wp = p ? w2.y : w2.x;
                    unsigned long long t2 = add2(xp, cp);
                    unsigned long long s2 = mul2(t2, t2);
                    unsigned long long p2 = fma2(s2, C3p, C1p);
                    unsigned long long u2 = mul2(p2, t2);
                    float ul, uh; upk2(u2, ul, uh);
                    float thl = tanh_approx(ul);
                    float thh = tanh_approx(uh);
                    unsigned long long th2 = pk2(thl, thh);
                    unsigned long long hx2 = mul2(t2, H2p);
                    unsigned long long g2  = fma2(hx2, th2, hx2);  // 0.5t(1+tanh)
                    acc2[j] = fma2(wp, g2, acc2[j]);
                }
            }
        }

        float acc[JT];
#pragma unroll
        for (int j = 0; j < JT; ++j) {
            float lo, hi; upk2(acc2[j], lo, hi);
            acc[j] = lo + hi;
        }
#pragma unroll
        for (int off = 16; off; off >>= 1)
#pragma unroll
            for (int j = 0; j < JT; ++j)
                acc[j] += __shfl_xor_sync(0xffffffffu, acc[j], off);

        if (lane == 0) {
#pragma unroll
            for (int j = 0; j < JT; ++j) {
                float logit = acc[j] + bias2;
                float en = ex2_approx(-1.44269504f * logit);
                red[warp][j] += rcp_approx(1.0f + en);
            }
        }
    }

    __syncthreads();
    if (tid < JT) {
        float s = 0.0f;
#pragma unroll
        for (int w = 0; w < 8; ++w) s += red[w][tid];
        out[i * VC + jt * JT + tid] = s * (1.0f / BC);
    }
}

// ---------------------------------------------------------------------------
extern "C" void kernel_launch(void* const* d_in, const int* in_sizes, int n_in,
                              void* d_out, int out_size) {
    const float* state  = (const float*)d_in[0];
    const float* action = (const float*)d_in[1];
    const float* embed  = (const float*)d_in[2];
    const float* W1     = (const float*)d_in[3];
    const float* b1     = (const float*)d_in[4];
    const float* W2     = (const float*)d_in[5];
    const float* b2     = (const float*)d_in[6];
    float* out          = (float*)d_out;

    gemm_pre_kernel<<<96, 256>>>(state, action, embed, W1);
    score_kernel<<<VC * (VC / JT), 256>>>(b1, W2, b2, out);
}

// round 6
// speedup vs baseline: 2.1786x; 1.1481x over previous
#include <cuda_runtime.h>
#include <math.h>

#define DIMC 512
#define HC   1024
#define BC   64
#define VC   64
#define JT   4

__device__ __align__(16) float g_pre[3 * BC * HC];

__device__ __forceinline__ float ex2_approx(float x) {
    float y; asm("ex2.approx.f32 %0, %1;" : "=f"(y) : "f"(x)); return y;
}
__device__ __forceinline__ float rcp_approx(float x) {
    float y; asm("rcp.approx.f32 %0, %1;" : "=f"(y) : "f"(x)); return y;
}
__device__ __forceinline__ float tanh_approx(float x) {
    float y; asm("tanh.approx.f32 %0, %1;" : "=f"(y) : "f"(x)); return y;
}
__device__ __forceinline__ unsigned long long pk2(float lo, float hi) {
    unsigned long long r; asm("mov.b64 %0, {%1,%2};" : "=l"(r) : "f"(lo), "f"(hi)); return r;
}
__device__ __forceinline__ void upk2(unsigned long long v, float& lo, float& hi) {
    asm("mov.b64 {%0,%1}, %2;" : "=f"(lo), "=f"(hi) : "l"(v));
}
__device__ __forceinline__ unsigned long long add2(unsigned long long a, unsigned long long b) {
    unsigned long long r; asm("add.rn.f32x2 %0, %1, %2;" : "=l"(r) : "l"(a), "l"(b)); return r;
}
__device__ __forceinline__ unsigned long long mul2(unsigned long long a, unsigned long long b) {
    unsigned long long r; asm("mul.rn.f32x2 %0, %1, %2;" : "=l"(r) : "l"(a), "l"(b)); return r;
}
__device__ __forceinline__ unsigned long long fma2(unsigned long long a, unsigned long long b, unsigned long long c) {
    unsigned long long r; asm("fma.rn.f32x2 %0, %1, %2, %3;" : "=l"(r) : "l"(a), "l"(b), "l"(c)); return r;
}

// Hendrycks tanh-form GELU: gelu(t) = 0.5*t*(1 + tanh(t*(C1 + C3*t^2)))
#define C1F (0.7978845608f)
#define C3F (0.0356774081f)

// ---------------------------------------------------------------------------
// Kernel 1: pre-activations. grid = 3*64 = 192 blocks, 128 threads.
// Block = 64 rows x 16 cols; thread = 1 row x 8 cols, warp-uniform col group.
// Register-prefetch double buffered over 32-k chunks.
// ---------------------------------------------------------------------------
__global__ __launch_bounds__(128) void gemm_pre_kernel(
        const float* __restrict__ state, const float* __restrict__ action,
        const float* __restrict__ embed, const float* __restrict__ W1) {
    const int m  = blockIdx.x / 64;        // 0..2
    const int ct = blockIdx.x % 64;        // cols ct*16 .. +16
    const int tid = threadIdx.x;           // 128

    __shared__ float As[64][33];
    __shared__ __align__(16) float Ws[32][20];

    const int r  = tid & 63;               // row (warp-contiguous)
    const int cg = tid >> 6;               // 0/1 -> cols cg*8..+8 (warp-uniform)

    float acc[8];
#pragma unroll
    for (int i = 0; i < 8; ++i) acc[i] = 0.0f;

    const float* Wbase = W1 + (size_t)(m * DIMC) * HC + ct * 16;

    float a_pref[16];
    float w_pref[4];

#pragma unroll
    for (int i = 0; i < 16; ++i) {
        int idx = tid + i * 128;           // 0..2047
        int rr = idx >> 5, k = idx & 31;
        if (m == 2) a_pref[i] = state[rr * DIMC + k] + action[rr * DIMC + k];
        else        a_pref[i] = embed[rr * DIMC + k];
    }
#pragma unroll
    for (int i = 0; i < 4; ++i) {
        int idx = tid + i * 128;           // 0..511
        int k = idx >> 4, c = idx & 15;
        w_pref[i] = Wbase[(size_t)k * HC + c];
    }

    for (int ch = 0; ch < DIMC / 32; ++ch) {
        __syncthreads();
#pragma unroll
        for (int i = 0; i < 16; ++i) {
            int idx = tid + i * 128;
            As[idx >> 5][idx & 31] = a_pref[i];
        }
#pragma unroll
        for (int i = 0; i < 4; ++i) {
            int idx = tid + i * 128;
            Ws[idx >> 4][idx & 15] = w_pref[i];
        }
        __syncthreads();

        if (ch < DIMC / 32 - 1) {
            const int k0 = (ch + 1) * 32;
#pragma unroll
            for (int i = 0; i < 16; ++i) {
                int idx = tid + i * 128;
                int rr = idx >> 5, k = idx & 31;
                if (m == 2) a_pref[i] = state[rr * DIMC + k0 + k] + action[rr * DIMC + k0 + k];
                else        a_pref[i] = embed[rr * DIMC + k0 + k];
            }
#pragma unroll
            for (int i = 0; i < 4; ++i) {
                int idx = tid + i * 128;
                int k = idx >> 4, c = idx & 15;
                w_pref[i] = Wbase[(size_t)(k0 + k) * HC + c];
            }
        }

#pragma unroll
        for (int k = 0; k < 32; ++k) {
            float a = As[r][k];
            float4 w0 = *reinterpret_cast<const float4*>(&Ws[k][cg * 8]);
            float4 w1 = *reinterpret_cast<const float4*>(&Ws[k][cg * 8 + 4]);
            acc[0] = fmaf(a, w0.x, acc[0]);
            acc[1] = fmaf(a, w0.y, acc[1]);
            acc[2] = fmaf(a, w0.z, acc[2]);
            acc[3] = fmaf(a, w0.w, acc[3]);
            acc[4] = fmaf(a, w1.x, acc[4]);
            acc[5] = fmaf(a, w1.y, acc[5]);
            acc[6] = fmaf(a, w1.z, acc[6]);
            acc[7] = fmaf(a, w1.w, acc[7]);
        }
    }

    float* out = g_pre + (size_t)(m * BC) * HC + (size_t)r * HC + ct * 16 + cg * 8;
    *reinterpret_cast<float4*>(out)     = make_float4(acc[0], acc[1], acc[2], acc[3]);
    *reinterpret_cast<float4*>(out + 4) = make_float4(acc[4], acc[5], acc[6], acc[7]);
}

// ---------------------------------------------------------------------------
// Kernel 2: scores. grid = 64*16 = 1024 blocks (i, j-tile of 4).
// 256 thr = 8 warps, warp-per-b. Packed f32x2 + MUFU.TANH.
// ---------------------------------------------------------------------------
__global__ __launch_bounds__(256, 5) void score_kernel(
        const float* __restrict__ b1, const float* __restrict__ W2,
        const float* __restrict__ b2, float* __restrict__ out) {
    const int i  = blockIdx.x >> 4;
    const int jt = blockIdx.x & 15;

    __shared__ __align__(16) float ce_s[JT][HC];
    __shared__ __align__(16) float w2s[HC];
    __shared__ float red[8][JT];

    const int tid  = threadIdx.x;
    const int warp = tid >> 5;
    const int lane = tid & 31;

    const float* cause  = g_pre;
    const float* effect = g_pre + BC * HC;
    const float* ctx    = g_pre + 2 * BC * HC;

    if (tid < 8 * JT) red[tid >> 2][tid & 3] = 0.0f;

    {
        const float4* c4 = reinterpret_cast<const float4*>(cause + i * HC);
        const float4* b4 = reinterpret_cast<const float4*>(b1);
        for (int t = tid; t < JT * HC / 4; t += 256) {
            int j = t >> 8, v = t & 255;
            float4 e4 = reinterpret_cast<const float4*>(effect + (jt * JT + j) * HC)[v];
            float4 cc = c4[v], bb = b4[v];
            float4 rr;
            rr.x = cc.x + e4.x + bb.x;
            rr.y = cc.y + e4.y + bb.y;
            rr.z = cc.z + e4.z + bb.z;
            rr.w = cc.w + e4.w + bb.w;
            reinterpret_cast<float4*>(ce_s[j])[v] = rr;
        }
        for (int t = tid; t < HC / 4; t += 256)
            reinterpret_cast<float4*>(w2s)[t] = reinterpret_cast<const float4*>(W2)[t];
    }
    __syncthreads();

    const unsigned long long C1p = pk2(C1F, C1F);
    const unsigned long long C3p = pk2(C3F, C3F);
    const unsigned long long H2p = pk2(0.5f, 0.5f);
    const float bias2 = b2[0];

    for (int bi = 0; bi < 8; ++bi) {
        const int b = bi * 8 + warp;
        const ulonglong2* ctx2 = reinterpret_cast<const ulonglong2*>(ctx + (size_t)b * HC);
        const ulonglong2* w22  = reinterpret_cast<const ulonglong2*>(w2s);

        unsigned long long acc2[JT];
#pragma unroll
        for (int j = 0; j < JT; ++j) acc2[j] = 0ull;

#pragma unroll 2
        for (int v = lane; v < HC / 4; v += 32) {
            const ulonglong2 x2 = ctx2[v];
            const ulonglong2 w2 = w22[v];
#pragma unroll
            for (int j = 0; j < JT; ++j) {
                const ulonglong2 c2 = reinterpret_cast<const ulonglong2*>(ce_s[j])[v];
#pragma unroll
                for (int p = 0; p < 2; ++p) {
                    unsigned long long xp = p ? x2.y : x2.x;
                    unsigned long long cp = p ? c2.y : c2.x;
                    unsigned long long wp = p ? w2.y : w2.x;
                    unsigned long long t2 = add2(xp, cp);
                    unsigned long long s2 = mul2(t2, t2);
                    unsigned long long p2 = fma2(s2, C3p, C1p);
                    unsigned long long u2 = mul2(p2, t2);
                    float ul, uh; upk2(u2, ul, uh);
                    float thl = tanh_approx(ul);
                    float thh = tanh_approx(uh);
                    unsigned long long th2 = pk2(thl, thh);
                    unsigned long long hx2 = mul2(t2, H2p);
                    unsigned long long g2  = fma2(hx2, th2, hx2);
                    acc2[j] = fma2(wp, g2, acc2[j]);
                }
            }
        }

        float acc[JT];
#pragma unroll
        for (int j = 0; j < JT; ++j) {
            float lo, hi; upk2(acc2[j], lo, hi);
            acc[j] = lo + hi;
        }
#pragma unroll
        for (int off = 16; off; off >>= 1)
#pragma unroll
            for (int j = 0; j < JT; ++j)
                acc[j] += __shfl_xor_sync(0xffffffffu, acc[j], off);

        if (lane == 0) {
#pragma unroll
            for (int j = 0; j < JT; ++j) {
                float logit = acc[j] + bias2;
                float en = ex2_approx(-1.44269504f * logit);
                red[warp][j] += rcp_approx(1.0f + en);
            }
        }
    }

    __syncthreads();
    if (tid < JT) {
        float s = 0.0f;
#pragma unroll
        for (int w = 0; w < 8; ++w) s += red[w][tid];
        out[i * VC + jt * JT + tid] = s * (1.0f / BC);
    }
}

// ---------------------------------------------------------------------------
extern "C" void kernel_launch(void* const* d_in, const int* in_sizes, int n_in,
                              void* d_out, int out_size) {
    const float* state  = (const float*)d_in[0];
    const float* action = (const float*)d_in[1];
    const float* embed  = (const float*)d_in[2];
    const float* W1     = (const float*)d_in[3];
    const float* b1     = (const float*)d_in[4];
    const float* W2     = (const float*)d_in[5];
    const float* b2     = (const float*)d_in[6];
    float* out          = (float*)d_out;

    gemm_pre_kernel<<<192, 128>>>(state, action, embed, W1);
    score_kernel<<<VC * (VC / JT), 256>>>(b1, W2, b2, out);
}